// round 13
// baseline (speedup 1.0000x reference)
#include <cuda_runtime.h>
#include <cuda_bf16.h>
#include <math.h>
#include <stdint.h>

// Problem constants
#define BSZ    256
#define HDIM   768
#define H3     2304
#define TSTEPS 128

// Tiling
#define JT       24               // j-columns per CTA (per gate)
#define NB       72               // 3 gates * JT rows of W per CTA
#define MTILE    64               // batch rows per CTA
#define NKC      12               // 64-wide k-chunks
#define NTHREADS 384              // 12 warps
#define NJB      (HDIM / JT)      // 32
#define NHALF    16               // producers per half-counter

// Dynamic SMEM layout (bytes)
//   W resident (bf16): [chunk(12)][row(72)][128B], SW128 = 110592
//   A resident (bf16 h): [chunk(12)][row(64)][128B], SW128 = 98304
#define WCH      (NB * 128)                    // 9216 per W chunk
#define WBYTES   (NKC * WCH)                   // 110592
#define AOFF     WBYTES
#define ACH      (MTILE * 128)                 // 8192 per A chunk
#define SMEM_DYN (AOFF + NKC * ACH)            // 208896
#define CSTRIDE  73                            // fp32 C row stride in epilogue

// ---------------------------------------------------------------------------
// Device globals
// ---------------------------------------------------------------------------
__device__ __align__(16) __nv_bfloat16 g_hb[2][BSZ * HDIM];  // bf16 h
__device__ __align__(16) __nv_bfloat16 g_wh[H3 * HDIM];      // bf16 W
__device__ float    g_dotp[TSTEPS * NJB * BSZ];
__device__ unsigned g_barg[4 * 64];   // [group][half] counters, 128B apart

// ---------------------------------------------------------------------------
// PTX helpers (baseline sm_80/90 features only — NO tcgen05)
// ---------------------------------------------------------------------------
__device__ __forceinline__ uint32_t smem_u32(const void* p) {
    uint32_t a;
    asm("{ .reg .u64 t; cvta.to.shared.u64 t, %1; cvt.u32.u64 %0, t; }"
        : "=r"(a) : "l"(p));
    return a;
}
__device__ __forceinline__ void cp16(uint32_t d, const void* s) {
    asm volatile("cp.async.cg.shared.global [%0], [%1], 16;" :: "r"(d), "l"(s));
}
__device__ __forceinline__ void cp_commit() {
    asm volatile("cp.async.commit_group;" ::: "memory");
}
template <int N>
__device__ __forceinline__ void cp_wait() {
    asm volatile("cp.async.wait_group %0;" :: "n"(N) : "memory");
}
__device__ __forceinline__ void ldsm_x4(uint32_t* r, uint32_t a) {
    asm volatile("ldmatrix.sync.aligned.m8n8.x4.shared.b16 {%0,%1,%2,%3}, [%4];"
                 : "=r"(r[0]), "=r"(r[1]), "=r"(r[2]), "=r"(r[3]) : "r"(a));
}
__device__ __forceinline__ void ldsm_x2(uint32_t* r, uint32_t a) {
    asm volatile("ldmatrix.sync.aligned.m8n8.x2.shared.b16 {%0,%1}, [%2];"
                 : "=r"(r[0]), "=r"(r[1]) : "r"(a));
}
__device__ __forceinline__ void mma_bf16(float* c, const uint32_t* a, const uint32_t* b) {
    asm volatile(
        "mma.sync.aligned.m16n8k16.row.col.f32.bf16.bf16.f32 "
        "{%0,%1,%2,%3}, {%4,%5,%6,%7}, {%8,%9}, {%0,%1,%2,%3};"
        : "+f"(c[0]), "+f"(c[1]), "+f"(c[2]), "+f"(c[3])
        : "r"(a[0]), "r"(a[1]), "r"(a[2]), "r"(a[3]), "r"(b[0]), "r"(b[1]));
}
#define SW128(o) ((o) ^ (((o) >> 3) & 0x70))

// fast gates: __expf (2-ulp MUFU) based; errors ~1e-6, far below bf16 noise
__device__ __forceinline__ float sigmoid_fast(float x) {
    return fdividef(1.0f, 1.0f + __expf(-x));
}
__device__ __forceinline__ float tanh_fast(float x) {
    return 1.0f - fdividef(2.0f, __expf(2.0f * x) + 1.0f);
}

// ---------------------------------------------------------------------------
// Prep kernels
// ---------------------------------------------------------------------------
__global__ void prep_w_kernel(const float* __restrict__ W) {
    int i = blockIdx.x * blockDim.x + threadIdx.x;
    if (i < H3 * HDIM) g_wh[i] = __float2bfloat16_rn(W[i]);
}
__global__ void prep_h_kernel(const float* __restrict__ ctx) {
    int i = blockIdx.x * blockDim.x + threadIdx.x;
    if (i < 4 * 64) g_barg[i] = 0u;
    if (i < BSZ * HDIM) g_hb[0][i] = __float2bfloat16_rn(ctx[i]);
}

// ---------------------------------------------------------------------------
// Persistent kernel: all 128 GRU steps.
// Grid (32, 4), 384 threads = 12 warps, warp tile 16x24 over CTA tile 64x72.
// Single-term bf16, A fully resident, split-half rendezvous per step.
// ---------------------------------------------------------------------------
__global__ __launch_bounds__(NTHREADS, 1) void persist_kernel(
    const float* __restrict__ context,
    const float* __restrict__ bias_ih,
    const float* __restrict__ bias_hh,
    const float* __restrict__ fc_w)
{
    extern __shared__ __align__(16) uint8_t smem[];
    __shared__ float sbr[JT], sbz[JT], sbni[JT], sbnh[JT], sfw[JT];

    const uint32_t sbase = smem_u32(smem);
    const int tid    = threadIdx.x;
    const int lane   = tid & 31;
    const int wid    = tid >> 5;
    const int warp_m = (wid & 3) * 16;     // 4 m-tiles of 16 (M=64)
    const int warp_n = (wid >> 2) * 24;    // 3 n-tiles of 24 (N=72)
    const int jb     = blockIdx.x;
    const int j0     = jb * JT;
    const int brow   = blockIdx.y * MTILE;
    unsigned* ctrH0  = &g_barg[blockIdx.y * 64];
    unsigned* ctrH1  = &g_barg[blockIdx.y * 64 + 32];
    unsigned* ctrOwn = (jb < NHALF) ? ctrH0 : ctrH1;

    // Epilogue ownership: threads 0..255 = (batch row, j-group of 6)
    const int eb  = tid >> 2;              // 0..63 (for tid<256)
    const int ejq = (tid & 3) * 6;         // 0,6,12,18

    // ---- stage resident W (bf16) into SMEM, SW128 swizzled ----
    for (int idx = tid; idx < NKC * NB * 8; idx += NTHREADS) {
        int ck  = idx / (NB * 8);
        int rem = idx - ck * (NB * 8);
        int r   = rem >> 3, cg = rem & 7;
        int wrow = (r / JT) * HDIM + j0 + (r % JT);
        size_t so = (size_t)wrow * HDIM + ck * 64 + cg * 8;
        uint32_t dst = (uint32_t)(ck * WCH) + SW128((uint32_t)(r * 128 + cg * 16));
        cp16(sbase + dst, g_wh + so);
    }
    cp_commit();   // W group

    if (tid < JT) {
        int j = j0 + tid;
        sbr[tid]  = bias_ih[j] + bias_hh[j];
        sbz[tid]  = bias_ih[HDIM + j] + bias_hh[HDIM + j];
        sbni[tid] = bias_ih[2 * HDIM + j];
        sbnh[tid] = bias_hh[2 * HDIM + j];
        sfw[tid]  = fc_w[j];
    }

    // fp32 h in registers: thread (tid<256) owns (brow+eb, j0+ejq..+5)
    float hreg[6];
    if (tid < 256) {
        const float* crow = context + (size_t)(brow + eb) * HDIM + j0 + ejq;
#pragma unroll
        for (int jj = 0; jj < 6; jj++) hreg[jj] = crow[jj];
    }
    __syncthreads();

    for (int t = 0; t < TSTEPS; t++) {
        const int rp = t & 1;
        const int wp = rp ^ 1;
        const __nv_bfloat16* __restrict__ hb = g_hb[rp];

        // ---- rendezvous: arrive own half, wait half-0 producers ----
        if (t > 0) {
            __syncthreads();               // all epilogue work done (and Csm reads)
            if (tid == 0) {
                __threadfence();
                atomicAdd(ctrOwn, 1u);
                const unsigned tgt = (unsigned)(NHALF * t);
                unsigned v;
                do { v = *(volatile unsigned*)ctrH0; } while (v < tgt);
                __threadfence();
            }
            __syncthreads();
        }

        float acc[3][4];
#pragma unroll
        for (int ni = 0; ni < 3; ni++)
#pragma unroll
            for (int q = 0; q < 4; q++) acc[ni][q] = 0.0f;

        // issue half (6 chunks = 3072 cp16, 8 per thread), one commit group
        auto issueHalf = [&](int half) {
            const int c0 = half * 6;
#pragma unroll
            for (int i = 0; i < 8; i++) {
                int idx = tid + i * NTHREADS;          // 0..3071
                int ck  = c0 + (idx >> 9);             // /512
                int rem = idx & 511;
                int r = rem >> 3, cg = rem & 7;
                uint32_t dst = (uint32_t)(AOFF + ck * ACH) +
                               SW128((uint32_t)(r * 128 + cg * 16));
                size_t so = (size_t)(brow + r) * HDIM + ck * 64 + cg * 8;
                cp16(sbase + dst, hb + so);
            }
            cp_commit();
        };

        auto compute = [&](int ck) {
            const uint32_t asb   = sbase + AOFF + (uint32_t)(ck * ACH);
            const uint32_t wbase = sbase + (uint32_t)(ck * WCH);
#pragma unroll
            for (int ks = 0; ks < 4; ks++) {
                const uint32_t kb = ks * 32;
                uint32_t ah[4], bw[3][2];
                {
                    uint32_t off = SW128(
                        (uint32_t)((warp_m + (lane & 15)) * 128) + kb +
                        ((lane >> 4) & 1) * 16);
                    ldsm_x4(ah, asb + off);
                }
#pragma unroll
                for (int ni = 0; ni < 3; ni++) {
                    uint32_t off = SW128(
                        (uint32_t)((warp_n + ni * 8 + (lane & 7)) * 128) + kb +
                        ((lane >> 3) & 1) * 16);
                    ldsm_x2(bw[ni], wbase + off);
                }
#pragma unroll
                for (int ni = 0; ni < 3; ni++)
                    mma_bf16(acc[ni], ah, bw[ni]);
            }
        };

        // ---- issue half 0, then gate half 1 on its producers ----
        issueHalf(0);
        if (t > 0) {
            if (tid == 0) {
                const unsigned tgt = (unsigned)(NHALF * t);
                unsigned v;
                do { v = *(volatile unsigned*)ctrH1; } while (v < tgt);
                __threadfence();
            }
            __syncthreads();
        }
        issueHalf(1);

        cp_wait<1>();          // half 0 (and W, step 0) complete
        __syncthreads();
#pragma unroll
        for (int ck = 0; ck < 6; ck++) compute(ck);
        cp_wait<0>();          // half 1 complete
        __syncthreads();       // all first-half computes done (A chunks 0-2 free)
#pragma unroll
        for (int ck = 6; ck < 12; ck++) compute(ck);

        // ---- C to SMEM (overlays A chunks 0-2; safe per mid-sync argument) ----
        float* Csm = (float*)(smem + AOFF);
        {
            const int r0 = lane >> 2, cpn = (lane & 3) * 2;
#pragma unroll
            for (int ni = 0; ni < 3; ni++) {
                int row = warp_m + r0;
                int col = warp_n + ni * 8 + cpn;
                Csm[row * CSTRIDE + col]           = acc[ni][0];
                Csm[row * CSTRIDE + col + 1]       = acc[ni][1];
                Csm[(row + 8) * CSTRIDE + col]     = acc[ni][2];
                Csm[(row + 8) * CSTRIDE + col + 1] = acc[ni][3];
            }
        }
        __syncthreads();

        // ---- gate epilogue: threads 0..255 = (row, j-group of 6) ----
        if (tid < 256) {
            const int b = brow + eb;
            uint32_t* __restrict__ hbo32 =
                (uint32_t*)(g_hb[wp] + (size_t)b * HDIM + j0 + ejq);
            const float* crow = Csm + eb * CSTRIDE;

            __nv_bfloat16 hout[6];
            float part = 0.0f;
#pragma unroll
            for (int q = 0; q < 6; q++) {
                const int jj = ejq + q;
                float rawr = crow[jj];
                float rawz = crow[JT + jj];
                float rawn = crow[2 * JT + jj];

                float rg = sigmoid_fast(sbr[jj] + rawr);
                float zg = sigmoid_fast(sbz[jj] + rawz);
                float ng = tanh_fast(sbni[jj] + rg * (rawn + sbnh[jj]));
                float hn = (1.0f - zg) * ng + zg * hreg[q];

                hreg[q] = hn;
                hout[q] = __float2bfloat16_rn(hn);
                part += hn * sfw[jj];
            }
#pragma unroll
            for (int q = 0; q < 3; q++) {
                uint32_t pk = (uint32_t)*(uint16_t*)&hout[2 * q] |
                              ((uint32_t)*(uint16_t*)&hout[2 * q + 1] << 16);
                hbo32[q] = pk;
            }
            part += __shfl_xor_sync(0xFFFFFFFFu, part, 1);
            part += __shfl_xor_sync(0xFFFFFFFFu, part, 2);
            if ((tid & 3) == 0)
                g_dotp[(size_t)t * NJB * BSZ + jb * BSZ + b] = part;
        }
        // next iteration's leading __syncthreads orders Csm/A reuse
    }
}

// ---------------------------------------------------------------------------
// Finalize: dot = fixed-order sum of 32 partials, softplus, scan, normalize
// ---------------------------------------------------------------------------
__device__ __forceinline__ float softplusf_(float x) {
    return (x > 0.0f) ? (x + log1pf(expf(-x))) : log1pf(expf(x));
}

__global__ __launch_bounds__(TSTEPS) void finalize_kernel(
    const int* __restrict__ num_pred,
    const float* __restrict__ fc_b,
    float* __restrict__ out)
{
    __shared__ float s[TSTEPS];
    const int b = blockIdx.x;
    const int t = threadIdx.x;

    float dot = fc_b[0];
    const float* p = g_dotp + (size_t)t * NJB * BSZ + b;
#pragma unroll
    for (int jbk = 0; jbk < NJB; jbk++) dot += p[jbk * BSZ];
    s[t] = softplusf_(dot);
    __syncthreads();

#pragma unroll
    for (int off = 1; off < TSTEPS; off <<= 1) {
        float v = (t >= off) ? s[t - off] : 0.0f;
        __syncthreads();
        s[t] += v;
        __syncthreads();
    }

    const int n = num_pred[b];
    int idx = n - 1;
    if (idx < 0) idx = 0;
    if (idx > TSTEPS - 1) idx = TSTEPS - 1;
    const float last = s[idx] + 1e-6f;

    float* orow = out + (size_t)b * (TSTEPS + 2);
    float val;
    if (t < n)       val = s[t] / last;
    else if (t == n) val = 1.0f;
    else             val = 0.0f;
    orow[t + 1] = val;

    if (t == 0) {
        orow[0] = 0.0f;
        orow[TSTEPS + 1] = (n == TSTEPS) ? 1.0f : 0.0f;
    }
}

// ---------------------------------------------------------------------------
// Launch. Inputs: 0 context 1 weight_ih(unused) 2 weight_hh 3 bias_ih
//                 4 bias_hh 5 fc_w 6 fc_b 7 num_pred_list 8 max_steps
// ---------------------------------------------------------------------------
extern "C" void kernel_launch(void* const* d_in, const int* in_sizes, int n_in,
                              void* d_out, int out_size)
{
    const float* context  = (const float*)d_in[0];
    const float* Whh      = (const float*)d_in[2];
    const float* bias_ih  = (const float*)d_in[3];
    const float* bias_hh  = (const float*)d_in[4];
    const float* fc_w     = (const float*)d_in[5];
    const float* fc_b     = (const float*)d_in[6];
    const int*   num_pred = (const int*)d_in[7];
    float*       out      = (float*)d_out;

    static bool attr_set = false;
    if (!attr_set) {
        cudaFuncSetAttribute(persist_kernel,
                             cudaFuncAttributeMaxDynamicSharedMemorySize, SMEM_DYN);
        attr_set = true;
    }

    prep_w_kernel<<<(H3 * HDIM + 255) / 256, 256>>>(Whh);
    prep_h_kernel<<<(BSZ * HDIM + 255) / 256, 256>>>(context);

    dim3 grid(NJB, BSZ / MTILE);  // (32, 4) = 128 CTAs, 1 per SM
    persist_kernel<<<grid, NTHREADS, SMEM_DYN>>>(context, bias_ih, bias_hh, fc_w);

    finalize_kernel<<<BSZ, TSTEPS>>>(num_pred, fc_b, out);
}

// round 14
// speedup vs baseline: 1.5809x; 1.5809x over previous
#include <cuda_runtime.h>
#include <cuda_bf16.h>
#include <math.h>
#include <stdint.h>

// Problem constants
#define BSZ    256
#define HDIM   768
#define H3     2304
#define TSTEPS 128

// Tiling
#define JT       24               // j-columns per CTA (per gate)
#define NB       72               // 3 gates * JT rows of W per CTA
#define MTILE    64               // batch rows per CTA
#define NKC      12               // 64-wide k-chunks
#define NTHREADS 384              // 12 warps
#define NJB      (HDIM / JT)      // 32
#define NGRP     32               // CTAs per barrier group (one batch-tile row)

// Dynamic SMEM layout (bytes)
//   W resident (bf16): [chunk(12)][row(72)][128B], SW128 = 110592
//   A resident (bf16 h): [chunk(12)][row(64)][128B], SW128 = 98304
#define WCH      (NB * 128)                    // 9216 per W chunk
#define WBYTES   (NKC * WCH)                   // 110592
#define AOFF     WBYTES
#define ACH      (MTILE * 128)                 // 8192 per A chunk
#define SMEM_DYN (AOFF + NKC * ACH)            // 208896
#define CSTRIDE  73                            // fp32 C row stride in epilogue

// ---------------------------------------------------------------------------
// Device globals
// ---------------------------------------------------------------------------
__device__ __align__(16) __nv_bfloat16 g_hb[2][BSZ * HDIM];  // bf16 h
__device__ __align__(16) __nv_bfloat16 g_wh[H3 * HDIM];      // bf16 W
__device__ float    g_dotp[TSTEPS * NJB * BSZ];
__device__ unsigned g_barg[4 * 32];   // 4 group counters, 128B apart

// ---------------------------------------------------------------------------
// PTX helpers (baseline sm_80/90 features only — NO tcgen05)
// ---------------------------------------------------------------------------
__device__ __forceinline__ uint32_t smem_u32(const void* p) {
    uint32_t a;
    asm("{ .reg .u64 t; cvta.to.shared.u64 t, %1; cvt.u32.u64 %0, t; }"
        : "=r"(a) : "l"(p));
    return a;
}
__device__ __forceinline__ void cp16(uint32_t d, const void* s) {
    asm volatile("cp.async.cg.shared.global [%0], [%1], 16;" :: "r"(d), "l"(s));
}
__device__ __forceinline__ void cp_commit() {
    asm volatile("cp.async.commit_group;" ::: "memory");
}
template <int N>
__device__ __forceinline__ void cp_wait() {
    asm volatile("cp.async.wait_group %0;" :: "n"(N) : "memory");
}
__device__ __forceinline__ void ldsm_x4(uint32_t* r, uint32_t a) {
    asm volatile("ldmatrix.sync.aligned.m8n8.x4.shared.b16 {%0,%1,%2,%3}, [%4];"
                 : "=r"(r[0]), "=r"(r[1]), "=r"(r[2]), "=r"(r[3]) : "r"(a));
}
__device__ __forceinline__ void ldsm_x2(uint32_t* r, uint32_t a) {
    asm volatile("ldmatrix.sync.aligned.m8n8.x2.shared.b16 {%0,%1}, [%2];"
                 : "=r"(r[0]), "=r"(r[1]) : "r"(a));
}
__device__ __forceinline__ void mma_bf16(float* c, const uint32_t* a, const uint32_t* b) {
    asm volatile(
        "mma.sync.aligned.m16n8k16.row.col.f32.bf16.bf16.f32 "
        "{%0,%1,%2,%3}, {%4,%5,%6,%7}, {%8,%9}, {%0,%1,%2,%3};"
        : "+f"(c[0]), "+f"(c[1]), "+f"(c[2]), "+f"(c[3])
        : "r"(a[0]), "r"(a[1]), "r"(a[2]), "r"(a[3]), "r"(b[0]), "r"(b[1]));
}
#define SW128(o) ((o) ^ (((o) >> 3) & 0x70))

// fast gates: __expf (2-ulp MUFU) based; errors ~1e-6, far below bf16 noise
// (validated R13: rel_err 2.8643e-5 vs 2.8655e-5 with precise versions)
__device__ __forceinline__ float sigmoid_fast(float x) {
    return fdividef(1.0f, 1.0f + __expf(-x));
}
__device__ __forceinline__ float tanh_fast(float x) {
    return 1.0f - fdividef(2.0f, __expf(2.0f * x) + 1.0f);
}

// ---------------------------------------------------------------------------
// Prep kernels
// ---------------------------------------------------------------------------
__global__ void prep_w_kernel(const float* __restrict__ W) {
    int i = blockIdx.x * blockDim.x + threadIdx.x;
    if (i < H3 * HDIM) g_wh[i] = __float2bfloat16_rn(W[i]);
}
__global__ void prep_h_kernel(const float* __restrict__ ctx) {
    int i = blockIdx.x * blockDim.x + threadIdx.x;
    if (i < 4 * 32) g_barg[i] = 0u;
    if (i < BSZ * HDIM) g_hb[0][i] = __float2bfloat16_rn(ctx[i]);
}

// ---------------------------------------------------------------------------
// Group barrier: 32 CTAs sharing one batch-tile row (all co-resident)
// ---------------------------------------------------------------------------
__device__ __forceinline__ void group_barrier(unsigned* ctr, unsigned target) {
    __syncthreads();
    if (threadIdx.x == 0) {
        __threadfence();
        atomicAdd(ctr, 1u);
        unsigned v;
        do { v = *(volatile unsigned*)ctr; } while (v < target);
        __threadfence();
    }
    __syncthreads();
}

// ---------------------------------------------------------------------------
// Persistent kernel: all 128 GRU steps.
// Grid (32, 4), 384 threads = 12 warps, warp tile 16x24 over CTA tile 64x72.
// Single-term bf16. A fully SMEM-resident per step; 2 waits + 2 syncs/step.
// (Structure == Round 12; only the epilogue math/stores differ.)
// ---------------------------------------------------------------------------
__global__ __launch_bounds__(NTHREADS, 1) void persist_kernel(
    const float* __restrict__ context,
    const float* __restrict__ bias_ih,
    const float* __restrict__ bias_hh,
    const float* __restrict__ fc_w)
{
    extern __shared__ __align__(16) uint8_t smem[];
    __shared__ float sbr[JT], sbz[JT], sbni[JT], sbnh[JT], sfw[JT];

    const uint32_t sbase = smem_u32(smem);
    const int tid    = threadIdx.x;
    const int lane   = tid & 31;
    const int wid    = tid >> 5;
    const int warp_m = (wid & 3) * 16;     // 4 m-tiles of 16 (M=64)
    const int warp_n = (wid >> 2) * 24;    // 3 n-tiles of 24 (N=72)
    const int jb     = blockIdx.x;
    const int j0     = jb * JT;
    const int brow   = blockIdx.y * MTILE;
    unsigned* bctr   = &g_barg[blockIdx.y * 32];

    // Epilogue ownership: threads 0..255 = (batch row, j-group of 6)
    const int eb  = tid >> 2;              // 0..63 (for tid<256)
    const int ejq = (tid & 3) * 6;         // 0,6,12,18

    // ---- stage resident W (bf16) into SMEM, SW128 swizzled ----
    for (int idx = tid; idx < NKC * NB * 8; idx += NTHREADS) {
        int ck  = idx / (NB * 8);
        int rem = idx - ck * (NB * 8);
        int r   = rem >> 3, cg = rem & 7;
        int wrow = (r / JT) * HDIM + j0 + (r % JT);
        size_t so = (size_t)wrow * HDIM + ck * 64 + cg * 8;
        uint32_t dst = (uint32_t)(ck * WCH) + SW128((uint32_t)(r * 128 + cg * 16));
        cp16(sbase + dst, g_wh + so);
    }
    cp_commit();   // W group

    if (tid < JT) {
        int j = j0 + tid;
        sbr[tid]  = bias_ih[j] + bias_hh[j];
        sbz[tid]  = bias_ih[HDIM + j] + bias_hh[HDIM + j];
        sbni[tid] = bias_ih[2 * HDIM + j];
        sbnh[tid] = bias_hh[2 * HDIM + j];
        sfw[tid]  = fc_w[j];
    }

    // fp32 h in registers: thread (tid<256) owns (brow+eb, j0+ejq..+5)
    float hreg[6];
    if (tid < 256) {
        const float* crow = context + (size_t)(brow + eb) * HDIM + j0 + ejq;
#pragma unroll
        for (int jj = 0; jj < 6; jj++) hreg[jj] = crow[jj];
    }
    __syncthreads();

    unsigned bar_target = 0;
    for (int t = 0; t < TSTEPS; t++) {
        const int rp = t & 1;
        const int wp = rp ^ 1;
        const __nv_bfloat16* __restrict__ hb = g_hb[rp];

        float acc[3][4];
#pragma unroll
        for (int ni = 0; ni < 3; ni++)
#pragma unroll
            for (int q = 0; q < 4; q++) acc[ni][q] = 0.0f;

        // issue half (6 chunks = 3072 cp16, 8 per thread), one commit group
        auto issueHalf = [&](int half) {
            const int c0 = half * 6;
#pragma unroll
            for (int i = 0; i < 8; i++) {
                int idx = tid + i * NTHREADS;          // 0..3071
                int ck  = c0 + (idx >> 9);             // /512
                int rem = idx & 511;
                int r = rem >> 3, cg = rem & 7;
                uint32_t dst = (uint32_t)(AOFF + ck * ACH) +
                               SW128((uint32_t)(r * 128 + cg * 16));
                size_t so = (size_t)(brow + r) * HDIM + ck * 64 + cg * 8;
                cp16(sbase + dst, hb + so);
            }
            cp_commit();
        };

        auto compute = [&](int ck) {
            const uint32_t asb   = sbase + AOFF + (uint32_t)(ck * ACH);
            const uint32_t wbase = sbase + (uint32_t)(ck * WCH);
#pragma unroll
            for (int ks = 0; ks < 4; ks++) {
                const uint32_t kb = ks * 32;
                uint32_t ah[4], bw[3][2];
                {
                    uint32_t off = SW128(
                        (uint32_t)((warp_m + (lane & 15)) * 128) + kb +
                        ((lane >> 4) & 1) * 16);
                    ldsm_x4(ah, asb + off);
                }
#pragma unroll
                for (int ni = 0; ni < 3; ni++) {
                    uint32_t off = SW128(
                        (uint32_t)((warp_n + ni * 8 + (lane & 7)) * 128) + kb +
                        ((lane >> 3) & 1) * 16);
                    ldsm_x2(bw[ni], wbase + off);
                }
#pragma unroll
                for (int ni = 0; ni < 3; ni++)
                    mma_bf16(acc[ni], ah, bw[ni]);
            }
        };

        // ---- 2-phase step: all A resident, 2 waits + 2 syncs ----
        issueHalf(0);
        issueHalf(1);
        cp_wait<1>();          // half 0 (and W, step 0) complete
        __syncthreads();
#pragma unroll
        for (int ck = 0; ck < 6; ck++) compute(ck);
        cp_wait<0>();          // half 1 complete
        __syncthreads();       // all first-half computes done (A chunks 0-2 free)
#pragma unroll
        for (int ck = 6; ck < 12; ck++) compute(ck);

        // ---- C to SMEM (overlays A chunks 0-2; safe per mid-sync argument) ----
        float* Csm = (float*)(smem + AOFF);
        {
            const int r0 = lane >> 2, cpn = (lane & 3) * 2;
#pragma unroll
            for (int ni = 0; ni < 3; ni++) {
                int row = warp_m + r0;
                int col = warp_n + ni * 8 + cpn;
                Csm[row * CSTRIDE + col]           = acc[ni][0];
                Csm[row * CSTRIDE + col + 1]       = acc[ni][1];
                Csm[(row + 8) * CSTRIDE + col]     = acc[ni][2];
                Csm[(row + 8) * CSTRIDE + col + 1] = acc[ni][3];
            }
        }
        __syncthreads();

        // ---- gate epilogue: threads 0..255 = (row, j-group of 6) ----
        if (tid < 256) {
            const int b = brow + eb;
            uint32_t* __restrict__ hbo32 =
                (uint32_t*)(g_hb[wp] + (size_t)b * HDIM + j0 + ejq);
            const float* crow = Csm + eb * CSTRIDE;

            __nv_bfloat16 hout[6];
            float part = 0.0f;
#pragma unroll
            for (int q = 0; q < 6; q++) {
                const int jj = ejq + q;
                float rawr = crow[jj];
                float rawz = crow[JT + jj];
                float rawn = crow[2 * JT + jj];

                float rg = sigmoid_fast(sbr[jj] + rawr);
                float zg = sigmoid_fast(sbz[jj] + rawz);
                float ng = tanh_fast(sbni[jj] + rg * (rawn + sbnh[jj]));
                float hn = (1.0f - zg) * ng + zg * hreg[q];

                hreg[q] = hn;
                hout[q] = __float2bfloat16_rn(hn);
                part += hn * sfw[jj];
            }
#pragma unroll
            for (int q = 0; q < 3; q++) {
                uint32_t pk = (uint32_t)*(uint16_t*)&hout[2 * q] |
                              ((uint32_t)*(uint16_t*)&hout[2 * q + 1] << 16);
                hbo32[q] = pk;
            }
            part += __shfl_xor_sync(0xFFFFFFFFu, part, 1);
            part += __shfl_xor_sync(0xFFFFFFFFu, part, 2);
            if ((tid & 3) == 0)
                g_dotp[(size_t)t * NJB * BSZ + jb * BSZ + b] = part;
        }

        // group barrier (leading __syncthreads also protects Csm/A reuse)
        bar_target += NGRP;
        if (t + 1 < TSTEPS) group_barrier(bctr, bar_target);
    }
}

// ---------------------------------------------------------------------------
// Finalize: dot = fixed-order sum of 32 partials, softplus, scan, normalize
// ---------------------------------------------------------------------------
__device__ __forceinline__ float softplusf_(float x) {
    return (x > 0.0f) ? (x + log1pf(expf(-x))) : log1pf(expf(x));
}

__global__ __launch_bounds__(TSTEPS) void finalize_kernel(
    const int* __restrict__ num_pred,
    const float* __restrict__ fc_b,
    float* __restrict__ out)
{
    __shared__ float s[TSTEPS];
    const int b = blockIdx.x;
    const int t = threadIdx.x;

    float dot = fc_b[0];
    const float* p = g_dotp + (size_t)t * NJB * BSZ + b;
#pragma unroll
    for (int jbk = 0; jbk < NJB; jbk++) dot += p[jbk * BSZ];
    s[t] = softplusf_(dot);
    __syncthreads();

#pragma unroll
    for (int off = 1; off < TSTEPS; off <<= 1) {
        float v = (t >= off) ? s[t - off] : 0.0f;
        __syncthreads();
        s[t] += v;
        __syncthreads();
    }

    const int n = num_pred[b];
    int idx = n - 1;
    if (idx < 0) idx = 0;
    if (idx > TSTEPS - 1) idx = TSTEPS - 1;
    const float last = s[idx] + 1e-6f;

    float* orow = out + (size_t)b * (TSTEPS + 2);
    float val;
    if (t < n)       val = s[t] / last;
    else if (t == n) val = 1.0f;
    else             val = 0.0f;
    orow[t + 1] = val;

    if (t == 0) {
        orow[0] = 0.0f;
        orow[TSTEPS + 1] = (n == TSTEPS) ? 1.0f : 0.0f;
    }
}

// ---------------------------------------------------------------------------
// Launch. Inputs: 0 context 1 weight_ih(unused) 2 weight_hh 3 bias_ih
//                 4 bias_hh 5 fc_w 6 fc_b 7 num_pred_list 8 max_steps
// ---------------------------------------------------------------------------
extern "C" void kernel_launch(void* const* d_in, const int* in_sizes, int n_in,
                              void* d_out, int out_size)
{
    const float* context  = (const float*)d_in[0];
    const float* Whh      = (const float*)d_in[2];
    const float* bias_ih  = (const float*)d_in[3];
    const float* bias_hh  = (const float*)d_in[4];
    const float* fc_w     = (const float*)d_in[5];
    const float* fc_b     = (const float*)d_in[6];
    const int*   num_pred = (const int*)d_in[7];
    float*       out      = (float*)d_out;

    static bool attr_set = false;
    if (!attr_set) {
        cudaFuncSetAttribute(persist_kernel,
                             cudaFuncAttributeMaxDynamicSharedMemorySize, SMEM_DYN);
        attr_set = true;
    }

    prep_w_kernel<<<(H3 * HDIM + 255) / 256, 256>>>(Whh);
    prep_h_kernel<<<(BSZ * HDIM + 255) / 256, 256>>>(context);

    dim3 grid(NJB, BSZ / MTILE);  // (32, 4) = 128 CTAs, 1 per SM
    persist_kernel<<<grid, NTHREADS, SMEM_DYN>>>(context, bias_ih, bias_hh, fc_w);

    finalize_kernel<<<BSZ, TSTEPS>>>(num_pred, fc_b, out);
}

// round 15
// speedup vs baseline: 1.7543x; 1.1097x over previous
#include <cuda_runtime.h>
#include <cuda_bf16.h>
#include <math.h>
#include <stdint.h>

// Problem constants
#define BSZ    256
#define HDIM   768
#define H3     2304
#define TSTEPS 128

// Tiling
#define JT       24               // j-columns per CTA (per gate)
#define NB       72               // 3 gates * JT rows of W per CTA
#define MTILE    64               // batch rows per CTA
#define NKC      12               // 64-wide k-chunks
#define NTHREADS 384              // 12 warps
#define NJB      (HDIM / JT)      // 32
#define NGRP     32               // CTAs per barrier group (one batch-tile row)

// Dynamic SMEM layout (bytes)
//   W resident (bf16): [chunk(12)][row(72)][128B], SW128 = 110592
//   A resident (bf16 h): [chunk(12)][row(64)][128B], SW128 = 98304
#define WCH      (NB * 128)                    // 9216 per W chunk
#define WBYTES   (NKC * WCH)                   // 110592
#define AOFF     WBYTES
#define ACH      (MTILE * 128)                 // 8192 per A chunk
#define SMEM_DYN (AOFF + NKC * ACH)            // 208896

// ---------------------------------------------------------------------------
// Device globals
// ---------------------------------------------------------------------------
__device__ __align__(16) __nv_bfloat16 g_hb[2][BSZ * HDIM];  // bf16 h
__device__ __align__(16) __nv_bfloat16 g_wh[H3 * HDIM];      // bf16 W
__device__ float    g_dotp[TSTEPS * NJB * 3 * BSZ];          // per-(jb,wn) partials
__device__ unsigned g_barg[4 * 32];   // 4 group counters, 128B apart

// ---------------------------------------------------------------------------
// PTX helpers (baseline sm_80/90 features only — NO tcgen05)
// ---------------------------------------------------------------------------
__device__ __forceinline__ uint32_t smem_u32(const void* p) {
    uint32_t a;
    asm("{ .reg .u64 t; cvta.to.shared.u64 t, %1; cvt.u32.u64 %0, t; }"
        : "=r"(a) : "l"(p));
    return a;
}
__device__ __forceinline__ void cp16(uint32_t d, const void* s) {
    asm volatile("cp.async.cg.shared.global [%0], [%1], 16;" :: "r"(d), "l"(s));
}
__device__ __forceinline__ void cp_commit() {
    asm volatile("cp.async.commit_group;" ::: "memory");
}
template <int N>
__device__ __forceinline__ void cp_wait() {
    asm volatile("cp.async.wait_group %0;" :: "n"(N) : "memory");
}
__device__ __forceinline__ void ldsm_x4(uint32_t* r, uint32_t a) {
    asm volatile("ldmatrix.sync.aligned.m8n8.x4.shared.b16 {%0,%1,%2,%3}, [%4];"
                 : "=r"(r[0]), "=r"(r[1]), "=r"(r[2]), "=r"(r[3]) : "r"(a));
}
__device__ __forceinline__ void ldsm_x2(uint32_t* r, uint32_t a) {
    asm volatile("ldmatrix.sync.aligned.m8n8.x2.shared.b16 {%0,%1}, [%2];"
                 : "=r"(r[0]), "=r"(r[1]) : "r"(a));
}
__device__ __forceinline__ void mma_bf16(float* c, const uint32_t* a, const uint32_t* b) {
    asm volatile(
        "mma.sync.aligned.m16n8k16.row.col.f32.bf16.bf16.f32 "
        "{%0,%1,%2,%3}, {%4,%5,%6,%7}, {%8,%9}, {%0,%1,%2,%3};"
        : "+f"(c[0]), "+f"(c[1]), "+f"(c[2]), "+f"(c[3])
        : "r"(a[0]), "r"(a[1]), "r"(a[2]), "r"(a[3]), "r"(b[0]), "r"(b[1]));
}
#define SW128(o) ((o) ^ (((o) >> 3) & 0x70))

// fast gates: __expf (2-ulp MUFU) based; validated R13/R14 (no rel_err impact)
__device__ __forceinline__ float sigmoid_fast(float x) {
    return fdividef(1.0f, 1.0f + __expf(-x));
}
__device__ __forceinline__ float tanh_fast(float x) {
    return 1.0f - fdividef(2.0f, __expf(2.0f * x) + 1.0f);
}

// ---------------------------------------------------------------------------
// Prep kernels
// ---------------------------------------------------------------------------
__global__ void prep_w_kernel(const float* __restrict__ W) {
    int i = blockIdx.x * blockDim.x + threadIdx.x;
    if (i < H3 * HDIM) g_wh[i] = __float2bfloat16_rn(W[i]);
}
__global__ void prep_h_kernel(const float* __restrict__ ctx) {
    int i = blockIdx.x * blockDim.x + threadIdx.x;
    if (i < 4 * 32) g_barg[i] = 0u;
    if (i < BSZ * HDIM) g_hb[0][i] = __float2bfloat16_rn(ctx[i]);
}

// ---------------------------------------------------------------------------
// Group barrier: 32 CTAs sharing one batch-tile row (all co-resident)
// ---------------------------------------------------------------------------
__device__ __forceinline__ void group_barrier(unsigned* ctr, unsigned target) {
    __syncthreads();
    if (threadIdx.x == 0) {
        __threadfence();
        atomicAdd(ctr, 1u);
        unsigned v;
        do { v = *(volatile unsigned*)ctr; } while (v < target);
        __threadfence();
    }
    __syncthreads();
}

// ---------------------------------------------------------------------------
// Persistent kernel: all 128 GRU steps.
// Grid (32, 4), 384 threads = 12 warps, warp tile 16x24 over CTA tile 64x72.
// B staged j-interleaved: chunk row rr -> (wn=rr/24, gate=(rr%24)/8, j8=rr%8)
// so each warp's fragment holds all 3 gates for its 8 j's -> in-register
// epilogue (no C SMEM roundtrip). 4 syncs/step.
// ---------------------------------------------------------------------------
__global__ __launch_bounds__(NTHREADS, 1) void persist_kernel(
    const float* __restrict__ context,
    const float* __restrict__ bias_ih,
    const float* __restrict__ bias_hh,
    const float* __restrict__ fc_w)
{
    extern __shared__ __align__(16) uint8_t smem[];
    __shared__ float sbr[JT], sbz[JT], sbni[JT], sbnh[JT], sfw[JT];

    const uint32_t sbase = smem_u32(smem);
    const int tid    = threadIdx.x;
    const int lane   = tid & 31;
    const int wid    = tid >> 5;
    const int warp_m = (wid & 3) * 16;     // 4 m-tiles of 16 (M=64)
    const int wn     = wid >> 2;           // 0..2: j-octet group
    const int warp_n = wn * 24;            // B tile row base
    const int jb     = blockIdx.x;
    const int j0     = jb * JT;
    const int brow   = blockIdx.y * MTILE;
    unsigned* bctr   = &g_barg[blockIdx.y * 32];

    // Fragment-local epilogue ownership:
    const int er0 = warp_m + (lane >> 2);          // rows er0, er0+8
    const int jl  = wn * 8 + (lane & 3) * 2;       // local j, +1

    // ---- stage resident W (bf16) into SMEM, SW128, j-interleaved rows ----
    for (int idx = tid; idx < NKC * NB * 8; idx += NTHREADS) {
        int ck  = idx / (NB * 8);
        int rem = idx - ck * (NB * 8);
        int r   = rem >> 3, cg = rem & 7;
        int wn_ = r / 24, g_ = (r % 24) >> 3, j8 = r & 7;
        int wrow = g_ * HDIM + j0 + wn_ * 8 + j8;
        size_t so = (size_t)wrow * HDIM + ck * 64 + cg * 8;
        uint32_t dst = (uint32_t)(ck * WCH) + SW128((uint32_t)(r * 128 + cg * 16));
        cp16(sbase + dst, g_wh + so);
    }
    cp_commit();   // W group

    if (tid < JT) {
        int j = j0 + tid;
        sbr[tid]  = bias_ih[j] + bias_hh[j];
        sbz[tid]  = bias_ih[HDIM + j] + bias_hh[HDIM + j];
        sbni[tid] = bias_ih[2 * HDIM + j];
        sbnh[tid] = bias_hh[2 * HDIM + j];
        sfw[tid]  = fc_w[j];
    }

    // fp32 h in registers, matching the C-fragment layout:
    // hreg[0]=(er0,jl) [1]=(er0,jl+1) [2]=(er0+8,jl) [3]=(er0+8,jl+1)
    float hreg[4];
    {
        const float* c0 = context + (size_t)(brow + er0) * HDIM + j0 + jl;
        const float* c8 = c0 + 8 * HDIM;
        hreg[0] = c0[0]; hreg[1] = c0[1];
        hreg[2] = c8[0]; hreg[3] = c8[1];
    }
    __syncthreads();

    unsigned bar_target = 0;
    for (int t = 0; t < TSTEPS; t++) {
        const int rp = t & 1;
        const int wp = rp ^ 1;
        const __nv_bfloat16* __restrict__ hb = g_hb[rp];

        float acc[3][4];
#pragma unroll
        for (int ni = 0; ni < 3; ni++)
#pragma unroll
            for (int q = 0; q < 4; q++) acc[ni][q] = 0.0f;

        // issue half (6 chunks = 3072 cp16, 8 per thread), one commit group
        auto issueHalf = [&](int half) {
            const int c0 = half * 6;
#pragma unroll
            for (int i = 0; i < 8; i++) {
                int idx = tid + i * NTHREADS;          // 0..3071
                int ck  = c0 + (idx >> 9);             // /512
                int rem = idx & 511;
                int r = rem >> 3, cg = rem & 7;
                uint32_t dst = (uint32_t)(AOFF + ck * ACH) +
                               SW128((uint32_t)(r * 128 + cg * 16));
                size_t so = (size_t)(brow + r) * HDIM + ck * 64 + cg * 8;
                cp16(sbase + dst, hb + so);
            }
            cp_commit();
        };

        auto compute = [&](int ck) {
            const uint32_t asb   = sbase + AOFF + (uint32_t)(ck * ACH);
            const uint32_t wbase = sbase + (uint32_t)(ck * WCH);
#pragma unroll
            for (int ks = 0; ks < 4; ks++) {
                const uint32_t kb = ks * 32;
                uint32_t ah[4], bw[3][2];
                {
                    uint32_t off = SW128(
                        (uint32_t)((warp_m + (lane & 15)) * 128) + kb +
                        ((lane >> 4) & 1) * 16);
                    ldsm_x4(ah, asb + off);
                }
#pragma unroll
                for (int ni = 0; ni < 3; ni++) {
                    uint32_t off = SW128(
                        (uint32_t)((warp_n + ni * 8 + (lane & 7)) * 128) + kb +
                        ((lane >> 3) & 1) * 16);
                    ldsm_x2(bw[ni], wbase + off);
                }
#pragma unroll
                for (int ni = 0; ni < 3; ni++)
                    mma_bf16(acc[ni], ah, bw[ni]);
            }
        };

        // ---- 2-phase step: all A resident, 2 waits + 2 syncs ----
        issueHalf(0);
        issueHalf(1);
        cp_wait<1>();          // half 0 (and W, step 0) complete
        __syncthreads();
#pragma unroll
        for (int ck = 0; ck < 6; ck++) compute(ck);
        cp_wait<0>();          // half 1 complete
        __syncthreads();
#pragma unroll
        for (int ck = 6; ck < 12; ck++) compute(ck);

        // ---- in-register gate epilogue (acc[gate][q] is thread-local) ----
        {
            const float br0 = sbr[jl],  br1 = sbr[jl + 1];
            const float bz0 = sbz[jl],  bz1 = sbz[jl + 1];
            const float bi0 = sbni[jl], bi1 = sbni[jl + 1];
            const float bh0 = sbnh[jl], bh1 = sbnh[jl + 1];
            const float fw0 = sfw[jl],  fw1 = sfw[jl + 1];

            float hn[4];
#pragma unroll
            for (int q = 0; q < 4; q++) {
                const bool c1 = (q & 1);          // j column (jl or jl+1)
                float rg = sigmoid_fast((c1 ? br1 : br0) + acc[0][q]);
                float zg = sigmoid_fast((c1 ? bz1 : bz0) + acc[1][q]);
                float ng = tanh_fast((c1 ? bi1 : bi0) +
                                     rg * (acc[2][q] + (c1 ? bh1 : bh0)));
                hn[q] = (1.0f - zg) * ng + zg * hreg[q];
                hreg[q] = hn[q];
            }

            // h store: pack 2 bf16 per row into one u32 (jl is even)
            uint32_t* hbo0 = (uint32_t*)(g_hb[wp] +
                             (size_t)(brow + er0) * HDIM + j0 + jl);
            uint32_t* hbo8 = (uint32_t*)((__nv_bfloat16*)hbo0 + 8 * HDIM);
            __nv_bfloat16 b0 = __float2bfloat16_rn(hn[0]);
            __nv_bfloat16 b1 = __float2bfloat16_rn(hn[1]);
            __nv_bfloat16 b2 = __float2bfloat16_rn(hn[2]);
            __nv_bfloat16 b3 = __float2bfloat16_rn(hn[3]);
            hbo0[0] = (uint32_t)*(uint16_t*)&b0 | ((uint32_t)*(uint16_t*)&b1 << 16);
            hbo8[0] = (uint32_t)*(uint16_t*)&b2 | ((uint32_t)*(uint16_t*)&b3 << 16);

            // fc partials: reduce over lane-quad (8 j's of this warp)
            float p0 = hn[0] * fw0 + hn[1] * fw1;    // row er0
            float p8 = hn[2] * fw0 + hn[3] * fw1;    // row er0+8
            p0 += __shfl_xor_sync(0xFFFFFFFFu, p0, 1);
            p0 += __shfl_xor_sync(0xFFFFFFFFu, p0, 2);
            p8 += __shfl_xor_sync(0xFFFFFFFFu, p8, 1);
            p8 += __shfl_xor_sync(0xFFFFFFFFu, p8, 2);
            if ((lane & 3) == 0) {
                float* dp = g_dotp + (size_t)t * (NJB * 3 * BSZ) +
                            (jb * 3 + wn) * BSZ + brow;
                dp[er0]     = p0;
                dp[er0 + 8] = p8;
            }
        }

        // group barrier (leading __syncthreads also protects A smem reuse)
        bar_target += NGRP;
        if (t + 1 < TSTEPS) group_barrier(bctr, bar_target);
    }
}

// ---------------------------------------------------------------------------
// Finalize: dot = fixed-order sum of 96 partials, softplus, scan, normalize
// ---------------------------------------------------------------------------
__device__ __forceinline__ float softplusf_(float x) {
    return (x > 0.0f) ? (x + log1pf(expf(-x))) : log1pf(expf(x));
}

__global__ __launch_bounds__(TSTEPS) void finalize_kernel(
    const int* __restrict__ num_pred,
    const float* __restrict__ fc_b,
    float* __restrict__ out)
{
    __shared__ float s[TSTEPS];
    const int b = blockIdx.x;
    const int t = threadIdx.x;

    float dot = fc_b[0];
    const float* p = g_dotp + (size_t)t * (NJB * 3 * BSZ) + b;
#pragma unroll
    for (int k = 0; k < NJB * 3; k++) dot += p[k * BSZ];
    s[t] = softplusf_(dot);
    __syncthreads();

#pragma unroll
    for (int off = 1; off < TSTEPS; off <<= 1) {
        float v = (t >= off) ? s[t - off] : 0.0f;
        __syncthreads();
        s[t] += v;
        __syncthreads();
    }

    const int n = num_pred[b];
    int idx = n - 1;
    if (idx < 0) idx = 0;
    if (idx > TSTEPS - 1) idx = TSTEPS - 1;
    const float last = s[idx] + 1e-6f;

    float* orow = out + (size_t)b * (TSTEPS + 2);
    float val;
    if (t < n)       val = s[t] / last;
    else if (t == n) val = 1.0f;
    else             val = 0.0f;
    orow[t + 1] = val;

    if (t == 0) {
        orow[0] = 0.0f;
        orow[TSTEPS + 1] = (n == TSTEPS) ? 1.0f : 0.0f;
    }
}

// ---------------------------------------------------------------------------
// Launch. Inputs: 0 context 1 weight_ih(unused) 2 weight_hh 3 bias_ih
//                 4 bias_hh 5 fc_w 6 fc_b 7 num_pred_list 8 max_steps
// ---------------------------------------------------------------------------
extern "C" void kernel_launch(void* const* d_in, const int* in_sizes, int n_in,
                              void* d_out, int out_size)
{
    const float* context  = (const float*)d_in[0];
    const float* Whh      = (const float*)d_in[2];
    const float* bias_ih  = (const float*)d_in[3];
    const float* bias_hh  = (const float*)d_in[4];
    const float* fc_w     = (const float*)d_in[5];
    const float* fc_b     = (const float*)d_in[6];
    const int*   num_pred = (const int*)d_in[7];
    float*       out      = (float*)d_out;

    static bool attr_set = false;
    if (!attr_set) {
        cudaFuncSetAttribute(persist_kernel,
                             cudaFuncAttributeMaxDynamicSharedMemorySize, SMEM_DYN);
        attr_set = true;
    }

    prep_w_kernel<<<(H3 * HDIM + 255) / 256, 256>>>(Whh);
    prep_h_kernel<<<(BSZ * HDIM + 255) / 256, 256>>>(context);

    dim3 grid(NJB, BSZ / MTILE);  // (32, 4) = 128 CTAs, 1 per SM
    persist_kernel<<<grid, NTHREADS, SMEM_DYN>>>(context, bias_ih, bias_hh, fc_w);

    finalize_kernel<<<BSZ, TSTEPS>>>(num_pred, fc_b, out);
}

// round 16
// speedup vs baseline: 1.7549x; 1.0003x over previous
#include <cuda_runtime.h>
#include <cuda_bf16.h>
#include <math.h>
#include <stdint.h>

// Problem constants
#define BSZ    256
#define HDIM   768
#define H3     2304
#define TSTEPS 128

// Tiling
#define JT       24               // j-columns per CTA (per gate)
#define NB       72               // 3 gates * JT rows of W per CTA
#define MTILE    64               // batch rows per CTA
#define NKC      12               // 64-wide k-chunks
#define NTHREADS 384              // 12 warps
#define NJB      (HDIM / JT)      // 32
#define NGRP     32               // CTAs per barrier group (one batch-tile row)

// Dynamic SMEM layout (bytes)
//   W resident (bf16): [chunk(12)][row(72)][128B], SW128 = 110592
//   A resident (bf16 h): [chunk(12)][row(64)][128B], SW128 = 98304
#define WCH      (NB * 128)                    // 9216 per W chunk
#define WBYTES   (NKC * WCH)                   // 110592
#define AOFF     WBYTES
#define ACH      (MTILE * 128)                 // 8192 per A chunk
#define SMEM_DYN (AOFF + NKC * ACH)            // 208896

// ---------------------------------------------------------------------------
// Device globals
// ---------------------------------------------------------------------------
__device__ __align__(16) __nv_bfloat16 g_hb[2][BSZ * HDIM];  // bf16 h
__device__ __align__(16) __nv_bfloat16 g_wh[H3 * HDIM];      // bf16 W
__device__ float    g_dotp[TSTEPS * NJB * 3 * BSZ];          // per-(jb,wn) partials
__device__ unsigned g_barg[4 * 32];   // 4 group counters, 128B apart

// ---------------------------------------------------------------------------
// PTX helpers (baseline sm_80/90 features only — NO tcgen05)
// ---------------------------------------------------------------------------
__device__ __forceinline__ uint32_t smem_u32(const void* p) {
    uint32_t a;
    asm("{ .reg .u64 t; cvta.to.shared.u64 t, %1; cvt.u32.u64 %0, t; }"
        : "=r"(a) : "l"(p));
    return a;
}
__device__ __forceinline__ void cp16(uint32_t d, const void* s) {
    asm volatile("cp.async.cg.shared.global [%0], [%1], 16;" :: "r"(d), "l"(s));
}
__device__ __forceinline__ void cp_commit() {
    asm volatile("cp.async.commit_group;" ::: "memory");
}
template <int N>
__device__ __forceinline__ void cp_wait() {
    asm volatile("cp.async.wait_group %0;" :: "n"(N) : "memory");
}
__device__ __forceinline__ void ldsm_x4(uint32_t* r, uint32_t a) {
    asm volatile("ldmatrix.sync.aligned.m8n8.x4.shared.b16 {%0,%1,%2,%3}, [%4];"
                 : "=r"(r[0]), "=r"(r[1]), "=r"(r[2]), "=r"(r[3]) : "r"(a));
}
__device__ __forceinline__ void ldsm_x2(uint32_t* r, uint32_t a) {
    asm volatile("ldmatrix.sync.aligned.m8n8.x2.shared.b16 {%0,%1}, [%2];"
                 : "=r"(r[0]), "=r"(r[1]) : "r"(a));
}
__device__ __forceinline__ void mma_bf16(float* c, const uint32_t* a, const uint32_t* b) {
    asm volatile(
        "mma.sync.aligned.m16n8k16.row.col.f32.bf16.bf16.f32 "
        "{%0,%1,%2,%3}, {%4,%5,%6,%7}, {%8,%9}, {%0,%1,%2,%3};"
        : "+f"(c[0]), "+f"(c[1]), "+f"(c[2]), "+f"(c[3])
        : "r"(a[0]), "r"(a[1]), "r"(a[2]), "r"(a[3]), "r"(b[0]), "r"(b[1]));
}
#define SW128(o) ((o) ^ (((o) >> 3) & 0x70))

// fast gates: __expf (2-ulp MUFU) based; validated R13-R15 (no rel_err impact)
__device__ __forceinline__ float sigmoid_fast(float x) {
    return fdividef(1.0f, 1.0f + __expf(-x));
}
__device__ __forceinline__ float tanh_fast(float x) {
    return 1.0f - fdividef(2.0f, __expf(2.0f * x) + 1.0f);
}

// ---------------------------------------------------------------------------
// Prep (single kernel: W convert + h0 convert + barrier counters)
// ---------------------------------------------------------------------------
__global__ void prep_kernel(const float* __restrict__ W,
                            const float* __restrict__ ctx) {
    int i = blockIdx.x * blockDim.x + threadIdx.x;
    if (i < H3 * HDIM) g_wh[i] = __float2bfloat16_rn(W[i]);
    if (i < BSZ * HDIM) g_hb[0][i] = __float2bfloat16_rn(ctx[i]);
    if (i < 4 * 32) g_barg[i] = 0u;
}

// ---------------------------------------------------------------------------
// Group barrier: 32 CTAs sharing one batch-tile row (all co-resident)
// ---------------------------------------------------------------------------
__device__ __forceinline__ void group_barrier(unsigned* ctr, unsigned target) {
    __syncthreads();
    if (threadIdx.x == 0) {
        __threadfence();
        atomicAdd(ctr, 1u);
        unsigned v;
        do { v = *(volatile unsigned*)ctr; } while (v < target);
        __threadfence();
    }
    __syncthreads();
}

// ---------------------------------------------------------------------------
// Persistent kernel: all 128 GRU steps.  (frozen at Round-15 form)
// Grid (32, 4), 384 threads = 12 warps, warp tile 16x24 over CTA tile 64x72.
// B staged j-interleaved so each warp's fragment holds all 3 gates for its
// 8 j's -> in-register epilogue. 4 syncs/step.
// ---------------------------------------------------------------------------
__global__ __launch_bounds__(NTHREADS, 1) void persist_kernel(
    const float* __restrict__ context,
    const float* __restrict__ bias_ih,
    const float* __restrict__ bias_hh,
    const float* __restrict__ fc_w)
{
    extern __shared__ __align__(16) uint8_t smem[];
    __shared__ float sbr[JT], sbz[JT], sbni[JT], sbnh[JT], sfw[JT];

    const uint32_t sbase = smem_u32(smem);
    const int tid    = threadIdx.x;
    const int lane   = tid & 31;
    const int wid    = tid >> 5;
    const int warp_m = (wid & 3) * 16;     // 4 m-tiles of 16 (M=64)
    const int wn     = wid >> 2;           // 0..2: j-octet group
    const int warp_n = wn * 24;            // B tile row base
    const int jb     = blockIdx.x;
    const int j0     = jb * JT;
    const int brow   = blockIdx.y * MTILE;
    unsigned* bctr   = &g_barg[blockIdx.y * 32];

    // Fragment-local epilogue ownership:
    const int er0 = warp_m + (lane >> 2);          // rows er0, er0+8
    const int jl  = wn * 8 + (lane & 3) * 2;       // local j, +1

    // ---- stage resident W (bf16) into SMEM, SW128, j-interleaved rows ----
    for (int idx = tid; idx < NKC * NB * 8; idx += NTHREADS) {
        int ck  = idx / (NB * 8);
        int rem = idx - ck * (NB * 8);
        int r   = rem >> 3, cg = rem & 7;
        int wn_ = r / 24, g_ = (r % 24) >> 3, j8 = r & 7;
        int wrow = g_ * HDIM + j0 + wn_ * 8 + j8;
        size_t so = (size_t)wrow * HDIM + ck * 64 + cg * 8;
        uint32_t dst = (uint32_t)(ck * WCH) + SW128((uint32_t)(r * 128 + cg * 16));
        cp16(sbase + dst, g_wh + so);
    }
    cp_commit();   // W group

    if (tid < JT) {
        int j = j0 + tid;
        sbr[tid]  = bias_ih[j] + bias_hh[j];
        sbz[tid]  = bias_ih[HDIM + j] + bias_hh[HDIM + j];
        sbni[tid] = bias_ih[2 * HDIM + j];
        sbnh[tid] = bias_hh[2 * HDIM + j];
        sfw[tid]  = fc_w[j];
    }

    // fp32 h in registers, matching the C-fragment layout:
    // hreg[0]=(er0,jl) [1]=(er0,jl+1) [2]=(er0+8,jl) [3]=(er0+8,jl+1)
    float hreg[4];
    {
        const float* c0 = context + (size_t)(brow + er0) * HDIM + j0 + jl;
        const float* c8 = c0 + 8 * HDIM;
        hreg[0] = c0[0]; hreg[1] = c0[1];
        hreg[2] = c8[0]; hreg[3] = c8[1];
    }
    __syncthreads();

    unsigned bar_target = 0;
    for (int t = 0; t < TSTEPS; t++) {
        const int rp = t & 1;
        const int wp = rp ^ 1;
        const __nv_bfloat16* __restrict__ hb = g_hb[rp];

        float acc[3][4];
#pragma unroll
        for (int ni = 0; ni < 3; ni++)
#pragma unroll
            for (int q = 0; q < 4; q++) acc[ni][q] = 0.0f;

        // issue half (6 chunks = 3072 cp16, 8 per thread), one commit group
        auto issueHalf = [&](int half) {
            const int c0 = half * 6;
#pragma unroll
            for (int i = 0; i < 8; i++) {
                int idx = tid + i * NTHREADS;          // 0..3071
                int ck  = c0 + (idx >> 9);             // /512
                int rem = idx & 511;
                int r = rem >> 3, cg = rem & 7;
                uint32_t dst = (uint32_t)(AOFF + ck * ACH) +
                               SW128((uint32_t)(r * 128 + cg * 16));
                size_t so = (size_t)(brow + r) * HDIM + ck * 64 + cg * 8;
                cp16(sbase + dst, hb + so);
            }
            cp_commit();
        };

        auto compute = [&](int ck) {
            const uint32_t asb   = sbase + AOFF + (uint32_t)(ck * ACH);
            const uint32_t wbase = sbase + (uint32_t)(ck * WCH);
#pragma unroll
            for (int ks = 0; ks < 4; ks++) {
                const uint32_t kb = ks * 32;
                uint32_t ah[4], bw[3][2];
                {
                    uint32_t off = SW128(
                        (uint32_t)((warp_m + (lane & 15)) * 128) + kb +
                        ((lane >> 4) & 1) * 16);
                    ldsm_x4(ah, asb + off);
                }
#pragma unroll
                for (int ni = 0; ni < 3; ni++) {
                    uint32_t off = SW128(
                        (uint32_t)((warp_n + ni * 8 + (lane & 7)) * 128) + kb +
                        ((lane >> 3) & 1) * 16);
                    ldsm_x2(bw[ni], wbase + off);
                }
#pragma unroll
                for (int ni = 0; ni < 3; ni++)
                    mma_bf16(acc[ni], ah, bw[ni]);
            }
        };

        // ---- 2-phase step: all A resident, 2 waits + 2 syncs ----
        issueHalf(0);
        issueHalf(1);
        cp_wait<1>();          // half 0 (and W, step 0) complete
        __syncthreads();
#pragma unroll
        for (int ck = 0; ck < 6; ck++) compute(ck);
        cp_wait<0>();          // half 1 complete
        __syncthreads();
#pragma unroll
        for (int ck = 6; ck < 12; ck++) compute(ck);

        // ---- in-register gate epilogue (acc[gate][q] is thread-local) ----
        {
            const float br0 = sbr[jl],  br1 = sbr[jl + 1];
            const float bz0 = sbz[jl],  bz1 = sbz[jl + 1];
            const float bi0 = sbni[jl], bi1 = sbni[jl + 1];
            const float bh0 = sbnh[jl], bh1 = sbnh[jl + 1];
            const float fw0 = sfw[jl],  fw1 = sfw[jl + 1];

            float hn[4];
#pragma unroll
            for (int q = 0; q < 4; q++) {
                const bool c1 = (q & 1);          // j column (jl or jl+1)
                float rg = sigmoid_fast((c1 ? br1 : br0) + acc[0][q]);
                float zg = sigmoid_fast((c1 ? bz1 : bz0) + acc[1][q]);
                float ng = tanh_fast((c1 ? bi1 : bi0) +
                                     rg * (acc[2][q] + (c1 ? bh1 : bh0)));
                hn[q] = (1.0f - zg) * ng + zg * hreg[q];
                hreg[q] = hn[q];
            }

            // h store: pack 2 bf16 per row into one u32 (jl is even)
            uint32_t* hbo0 = (uint32_t*)(g_hb[wp] +
                             (size_t)(brow + er0) * HDIM + j0 + jl);
            uint32_t* hbo8 = (uint32_t*)((__nv_bfloat16*)hbo0 + 8 * HDIM);
            __nv_bfloat16 b0 = __float2bfloat16_rn(hn[0]);
            __nv_bfloat16 b1 = __float2bfloat16_rn(hn[1]);
            __nv_bfloat16 b2 = __float2bfloat16_rn(hn[2]);
            __nv_bfloat16 b3 = __float2bfloat16_rn(hn[3]);
            hbo0[0] = (uint32_t)*(uint16_t*)&b0 | ((uint32_t)*(uint16_t*)&b1 << 16);
            hbo8[0] = (uint32_t)*(uint16_t*)&b2 | ((uint32_t)*(uint16_t*)&b3 << 16);

            // fc partials: reduce over lane-quad (8 j's of this warp)
            float p0 = hn[0] * fw0 + hn[1] * fw1;    // row er0
            float p8 = hn[2] * fw0 + hn[3] * fw1;    // row er0+8
            p0 += __shfl_xor_sync(0xFFFFFFFFu, p0, 1);
            p0 += __shfl_xor_sync(0xFFFFFFFFu, p0, 2);
            p8 += __shfl_xor_sync(0xFFFFFFFFu, p8, 1);
            p8 += __shfl_xor_sync(0xFFFFFFFFu, p8, 2);
            if ((lane & 3) == 0) {
                float* dp = g_dotp + (size_t)t * (NJB * 3 * BSZ) +
                            (jb * 3 + wn) * BSZ + brow;
                dp[er0]     = p0;
                dp[er0 + 8] = p8;
            }
        }

        // group barrier (leading __syncthreads also protects A smem reuse)
        bar_target += NGRP;
        if (t + 1 < TSTEPS) group_barrier(bctr, bar_target);
    }
}

// ---------------------------------------------------------------------------
// Finalize: 512 threads/block; thread (t = tid>>2, q = tid&3) sums 24 of the
// 96 partials, quad-shfl reduce (fixed tree order -> deterministic), then the
// first 128 threads run softplus + scan + normalize + scatter.
// ---------------------------------------------------------------------------
__device__ __forceinline__ float softplusf_(float x) {
    return (x > 0.0f) ? (x + log1pf(expf(-x))) : log1pf(expf(x));
}

__global__ __launch_bounds__(512) void finalize_kernel(
    const int* __restrict__ num_pred,
    const float* __restrict__ fc_b,
    float* __restrict__ out)
{
    __shared__ float s[TSTEPS];
    const int b   = blockIdx.x;
    const int tid = threadIdx.x;
    const int t   = tid >> 2;
    const int q   = tid & 3;

    // partial sum over 24 of 96 slots (quad threads interleave by lane for
    // contiguous shfl tree; order fixed -> deterministic)
    float part = 0.0f;
    const float* p = g_dotp + (size_t)t * (NJB * 3 * BSZ) + b;
#pragma unroll
    for (int k = 0; k < 24; k++) part += p[(q * 24 + k) * BSZ];
    part += __shfl_xor_sync(0xFFFFFFFFu, part, 1);
    part += __shfl_xor_sync(0xFFFFFFFFu, part, 2);
    if (q == 0) s[t] = softplusf_(part + fc_b[0]);
    __syncthreads();

    if (tid < TSTEPS) {
        // Hillis-Steele scan over the 128 values (uses 4 warps)
#pragma unroll
        for (int off = 1; off < TSTEPS; off <<= 1) {
            float v = (tid >= off) ? s[tid - off] : 0.0f;
            __syncwarp();
            asm volatile("bar.sync 1, 128;" ::: "memory");
            s[tid] += v;
            asm volatile("bar.sync 1, 128;" ::: "memory");
        }

        const int n = num_pred[b];
        int idx = n - 1;
        if (idx < 0) idx = 0;
        if (idx > TSTEPS - 1) idx = TSTEPS - 1;
        const float last = s[idx] + 1e-6f;

        float* orow = out + (size_t)b * (TSTEPS + 2);
        float val;
        if (tid < n)       val = s[tid] / last;
        else if (tid == n) val = 1.0f;
        else               val = 0.0f;
        orow[tid + 1] = val;

        if (tid == 0) {
            orow[0] = 0.0f;
            orow[TSTEPS + 1] = (n == TSTEPS) ? 1.0f : 0.0f;
        }
    }
}

// ---------------------------------------------------------------------------
// Launch. Inputs: 0 context 1 weight_ih(unused) 2 weight_hh 3 bias_ih
//                 4 bias_hh 5 fc_w 6 fc_b 7 num_pred_list 8 max_steps
// ---------------------------------------------------------------------------
extern "C" void kernel_launch(void* const* d_in, const int* in_sizes, int n_in,
                              void* d_out, int out_size)
{
    const float* context  = (const float*)d_in[0];
    const float* Whh      = (const float*)d_in[2];
    const float* bias_ih  = (const float*)d_in[3];
    const float* bias_hh  = (const float*)d_in[4];
    const float* fc_w     = (const float*)d_in[5];
    const float* fc_b     = (const float*)d_in[6];
    const int*   num_pred = (const int*)d_in[7];
    float*       out      = (float*)d_out;

    static bool attr_set = false;
    if (!attr_set) {
        cudaFuncSetAttribute(persist_kernel,
                             cudaFuncAttributeMaxDynamicSharedMemorySize, SMEM_DYN);
        attr_set = true;
    }

    prep_kernel<<<(H3 * HDIM + 255) / 256, 256>>>(Whh, context);

    dim3 grid(NJB, BSZ / MTILE);  // (32, 4) = 128 CTAs, 1 per SM
    persist_kernel<<<grid, NTHREADS, SMEM_DYN>>>(context, bias_ih, bias_hh, fc_w);

    finalize_kernel<<<BSZ, 512>>>(num_pred, fc_b, out);
}